// round 15
// baseline (speedup 1.0000x reference)
#include <cuda_runtime.h>
#include <cuda_pipeline.h>
#include <cstdint>

#define B 64
#define P 8732
#define C 81
#define O 32
#define RPB 128            // rows per lse block (B*P = 558848 = 128*4366)
#define NSLICE 16          // match blocks per batch item
#define BATCH_STRIDE (NSLICE * 16 * 32)   // 8192 priors per warp-sweep
#define NMATCH (NSLICE * B)               // 1024 match blocks
#define NLSE (B * P / RPB)                // 4366 lse blocks
#define GRID_TOTAL (NMATCH + NLSE)        // 5390
#define TSLICE 8                          // tail blocks per batch
#define TCHUNK 1092                       // ceil(P/TSLICE)
#define PPAD (18 * 512)                   // padded select sweep (>= P)

#define NEG_INF (__int_as_float(0xff800000))

// ---------------- scratch (device globals; no allocation anywhere) ----------
__device__ unsigned long long g_obj_slice[B * NSLICE * O]; // (ov_bits<<32)|~p
__device__ int   g_match[B * P];                 // packed (obj<<8)|tc per prior
__device__ float g_lse[B * P];
__device__ float g_bg[B * P];                    // lse - s0
__device__ float g_mined[B * P];
__device__ int   g_num_pos[B];
__device__ float g_neg_sum[B];
__device__ int   g_row_done[B];
__device__ float g_pos_ce;
__device__ float g_sl1;
__device__ int   g_done;

// ---------------- helpers ----------------------------------------------------
__device__ __forceinline__ unsigned okey(float f) {
    unsigned u = __float_as_uint(f);
    return (u & 0x80000000u) ? ~u : (u | 0x80000000u);
}
__device__ __forceinline__ float fromkey(unsigned k) {
    unsigned u = (k & 0x80000000u) ? (k & 0x7FFFFFFFu) : ~k;
    return __uint_as_float(u);
}
__device__ __forceinline__ float smoothl1(float d) {
    float a = fabsf(d);
    return (a < 1.0f) ? 0.5f * a * a : a - 0.5f;
}

// ---------------- K1: role-partitioned fused kernel (R13-proven) -------------
__global__ void __launch_bounds__(512, 2) fused_kernel(
        const float* __restrict__ scores,
        const float* __restrict__ boxes,
        const int*   __restrict__ labels,
        const float* __restrict__ priors) {
    int bid = blockIdx.x;
    int tid = threadIdx.x;
    bool is_match = (bid % 5 == 0) && (bid < 5 * NMATCH);

    if (is_match) {
        int mid = bid / 5;               // 0..1023
        int b = mid >> 4;                // batch
        int blk = mid & 15;              // slice
        int wid = tid >> 5;
        int lane = tid & 31;
        __shared__ float4 sbox[O];
        __shared__ float  sarea[O];
        __shared__ int    slab[O];
        __shared__ unsigned swkey[16][O];
        if (tid < O) {
            float4 bx = ((const float4*)boxes)[b * O + tid];
            sbox[tid] = bx;
            sarea[tid] = (bx.z - bx.x) * (bx.w - bx.y);
            slab[tid] = labels[b * O + tid];
        }
        if (mid == 0) {                  // init accumulators consumed by K2
            if (tid < B) { g_num_pos[tid] = 0; g_neg_sum[tid] = 0.0f; g_row_done[tid] = 0; }
            if (tid == 0) { g_pos_ce = 0.0f; g_sl1 = 0.0f; g_done = 0; }
        }
        __syncthreads();

        int gwarp = blk * 16 + wid;
        unsigned runB = 0u;

        for (int batch = 0; batch < 2; batch++) {
            int pbase = batch * BATCH_STRIDE + gwarp * 32;
            if (pbase >= P) break;
            int p = pbase + lane;
            bool valid = (p < P);
            int pc = valid ? p : (P - 1);

            float4 pr = ((const float4*)priors)[pc];
            float px0 = pr.x - 0.5f * pr.z, py0 = pr.y - 0.5f * pr.w;
            float px1 = pr.x + 0.5f * pr.z, py1 = pr.y + 0.5f * pr.w;
            float parea = pr.z * pr.w;

            unsigned bestA = 0u;
#pragma unroll
            for (int o = 0; o < O; o++) {
                float4 bx = sbox[o];
                float lx = fmaxf(bx.x, px0), ly = fmaxf(bx.y, py0);
                float hx = fminf(bx.z, px1), hy = fminf(bx.w, py1);
                float w = fmaxf(hx - lx, 0.0f), h = fmaxf(hy - ly, 0.0f);
                float inter = w * h;
                float ov = __fdividef(inter, sarea[o] + parea - inter);
                unsigned ob = __float_as_uint(ov);
                bestA = max(bestA, (ob & 0xFFFFFFE0u) | (unsigned)(31 - o));
                unsigned keyB = valid
                    ? ((ob & 0xFFFFFF80u) | (unsigned)((3 - batch) << 5) | (unsigned)(31 - lane))
                    : 0u;
                unsigned m = __reduce_max_sync(0xFFFFFFFFu, keyB);
                if (lane == o) runB = max(runB, m);
            }
            if (valid) {
                int bo = 31 - (int)(bestA & 31u);
                float bov = __uint_as_float(bestA & 0xFFFFFFE0u);
                int tc = (bov < 0.5f) ? 0 : slab[bo];
                g_match[b * P + p] = (bo << 8) | tc;
            }
        }

        swkey[wid][lane] = runB;
        __syncthreads();

        if (tid < O) {
            int o = tid;
            unsigned long long best = 0ULL;
#pragma unroll
            for (int w = 0; w < 16; w++) {
                unsigned k = swkey[w][o];
                int batch = 3 - (int)((k >> 5) & 3u);
                int ln = 31 - (int)(k & 31u);
                unsigned p = (unsigned)(batch * BATCH_STRIDE + (blk * 16 + w) * 32 + ln);
                unsigned long long cand =
                    ((unsigned long long)(k & 0xFFFFFF80u) << 32) | (0xFFFFFFFFu - p);
                if (cand > best) best = cand;
            }
            g_obj_slice[(b * NSLICE + blk) * O + o] = best;
        }
    } else {
        // LSE role: pure streaming
        int lse_id = bid - min((bid + 4) / 5, NMATCH);   // 0..4365
        __shared__ __align__(16) float sm[RPB * C];      // 41472 bytes
        int wid = tid >> 5;
        int lane = tid & 31;
        size_t row0 = (size_t)lse_id * RPB;

        {
            const char* gsrc = (const char*)(scores + (row0 + wid * 8) * C);
            char* sdst = (char*)(sm + wid * 8 * C);
#pragma unroll
            for (int i = lane; i < 162; i += 32)
                __pipeline_memcpy_async(sdst + i * 16, gsrc + i * 16, 16);
            __pipeline_commit();
            __pipeline_wait_prior(0);
            __syncwarp();
        }

        int k = tid >> 2;
        int q = tid & 3;
        const float* my = sm + k * C;

        float sa[4] = {0.f, 0.f, 0.f, 0.f};
#pragma unroll
        for (int it = 0; it < 24; it++) {
            int g = it >> 3, e = it & 7;
            int j = g * 32 + (q << 3) + e;
            if (j < C) sa[it & 3] += __expf(my[j]);
        }
        float sum = (sa[0] + sa[1]) + (sa[2] + sa[3]);
        sum += __shfl_xor_sync(0xFFFFFFFFu, sum, 1);
        sum += __shfl_xor_sync(0xFFFFFFFFu, sum, 2);
        float lse = __logf(sum);

        if (q == 0) {
            int r = (int)row0 + k;
            g_lse[r] = lse;
            g_bg[r] = lse - my[0];
        }
    }
}

// ---------------- K2: parallel tail — 8 slice blocks per batch ---------------
__global__ void __launch_bounds__(512) tail_kernel(
        const float* __restrict__ locs,
        const float* __restrict__ scores,
        const float* __restrict__ boxes,
        const int*   __restrict__ labels,
        const float* __restrict__ priors,
        float* __restrict__ out) {
    int s = blockIdx.x;                            // slice 0..7
    int b = blockIdx.y;                            // batch
    int tid = threadIdx.x;
    int lane = tid & 31;

    __shared__ float sm_mined[P];                  // 34928 B
    __shared__ unsigned spF[O];
    __shared__ int slabF[O];
    __shared__ int s_np;
    __shared__ float s_ce, s_sl1;
    __shared__ int strig;

    // resolve forced priors (redundant per slice, cheap)
    if (tid < O) {
        unsigned long long m = 0ULL;
#pragma unroll
        for (int sl = 0; sl < NSLICE; sl++)
            m = max(m, g_obj_slice[(b * NSLICE + sl) * O + tid]);
        spF[tid] = 0xFFFFFFFFu - (unsigned)(m & 0xFFFFFFFFu);
        slabF[tid] = labels[b * O + tid];
    }
    if (tid == 0) { s_np = 0; s_ce = 0.0f; s_sl1 = 0.0f; }
    __syncthreads();

    int pstart = s * TCHUNK;
    int pend = min(P, pstart + TCHUNK);

    // sweep this slice: mined + positive losses (fold forced priors inline)
    for (int p = pstart + tid; p < pend; p += 512) {
        int r = b * P + p;
        int mm = g_match[r];
        int tc = mm & 0xFF;
        int obj = mm >> 8;
#pragma unroll
        for (int o = 0; o < O; o++) {              // ascending: last (highest o) wins
            if (spF[o] == (unsigned)p) { tc = slabF[o]; obj = o; }
        }
        float mined;
        if (tc > 0) {
            float lse = g_lse[r];
            float stc = scores[(size_t)r * C + tc];
            atomicAdd(&s_ce, lse - stc);
            atomicAdd(&s_np, 1);
            float4 bx = ((const float4*)boxes)[b * O + obj];
            float4 pr = ((const float4*)priors)[p];
            float cx = 0.5f * (bx.x + bx.z), cy = 0.5f * (bx.y + bx.w);
            float w = bx.z - bx.x, h = bx.w - bx.y;
            float t0 = (cx - pr.x) * 10.0f / pr.z;
            float t1 = (cy - pr.y) * 10.0f / pr.w;
            float t2 = __logf(w / pr.z) * 5.0f;
            float t3 = __logf(h / pr.w) * 5.0f;
            float4 pl = ((const float4*)locs)[r];
            float sl = smoothl1(pl.x - t0) + smoothl1(pl.y - t1) +
                       smoothl1(pl.z - t2) + smoothl1(pl.w - t3);
            atomicAdd(&s_sl1, sl);
            mined = NEG_INF;
        } else {
            mined = g_bg[r];
        }
        g_mined[r] = mined;
    }
    __syncthreads();

    if (tid == 0) {                                // publish slice accumulators
        if (s_np) atomicAdd(&g_num_pos[b], s_np);
        atomicAdd(&g_pos_ce, s_ce);
        atomicAdd(&g_sl1, s_sl1);
        __threadfence();                           // mined + counters visible
        int c = atomicAdd(&g_row_done[b], pend - pstart) + (pend - pstart);
        strig = (c == P);
    }
    __syncthreads();

    if (!strig) return;
    // ======== last slice block of batch b: smem radix-select top-K ==========
    __threadfence();
    __shared__ int hist[256];
    __shared__ int ssum[256];
    __shared__ int wtot[8];
    __shared__ unsigned sprefix;
    __shared__ int sK;
    __shared__ float swsum[16];
    __shared__ int slastf;

    for (int p = tid; p < P; p += 512)
        sm_mined[p] = *(volatile float*)&g_mined[b * P + p];
    int np = *(volatile int*)&g_num_pos[b];
    int K = min(3 * np, P - np);
    float result = 0.0f;
    __syncthreads();

    if (K > 0) {
        if (tid == 0) { sprefix = 0u; sK = K; }
        __syncthreads();
        for (int shift = 24; shift >= 0; shift -= 8) {
            if (tid < 256) hist[tid] = 0;
            __syncthreads();
            unsigned prefix = sprefix;
            int Kr = sK;
            // warp-aggregated histogram: keys are highly concentrated, so
            // same-bin lanes combine into ONE atomic (ATOMS same-addr is 32cyc/warp)
            for (int p = tid; p < PPAD; p += 512) {
                unsigned bin = 0xFFFFFFFFu;        // sentinel: no contribution
                if (p < P) {
                    unsigned k = okey(sm_mined[p]);
                    if (shift == 24 || (k >> (shift + 8)) == prefix)
                        bin = (k >> shift) & 255u;
                }
                unsigned mmask = __match_any_sync(0xFFFFFFFFu, bin);
                if (bin != 0xFFFFFFFFu && (int)lane == __ffs(mmask) - 1)
                    atomicAdd(&hist[bin], __popc(mmask));
            }
            __syncthreads();
            int v = 0;
            int w = tid >> 5, l = tid & 31;
            if (tid < 256) {
                v = hist[tid];
#pragma unroll
                for (int off = 1; off < 32; off <<= 1) {
                    int u = __shfl_down_sync(0xFFFFFFFFu, v, off);
                    if (l + off < 32) v += u;
                }
                if (l == 0) wtot[w] = v;
            }
            __syncthreads();
            if (tid < 256) {
                int add = 0;
#pragma unroll
                for (int g = 1; g < 8; g++) if (w + g < 8) add += wtot[w + g];
                ssum[tid] = v + add;
            }
            __syncthreads();
            if (tid < 256) {
                int mine = ssum[tid];
                int nxt = (tid < 255) ? ssum[tid + 1] : 0;
                if (mine >= Kr && nxt < Kr) {
                    sprefix = (prefix << 8) | (unsigned)tid;
                    sK = Kr - nxt;
                }
            }
            __syncthreads();
        }
        unsigned T = sprefix;
        int rr = sK;
        float Tval = fromkey(T);

        float sum = 0.0f;
        for (int p = tid; p < P; p += 512) {
            float v2 = sm_mined[p];
            if (okey(v2) > T) sum += v2;
        }
#pragma unroll
        for (int off = 16; off; off >>= 1) sum += __shfl_xor_sync(0xFFFFFFFFu, sum, off);
        if ((tid & 31) == 0) swsum[tid >> 5] = sum;
        __syncthreads();
        if (tid == 0) {
            float tot = 0.0f;
#pragma unroll
            for (int i = 0; i < 16; i++) tot += swsum[i];
            result = tot + (float)rr * Tval;
        }
    }

    if (tid == 0) {
        g_neg_sum[b] = result;
        __threadfence();
        int d = atomicAdd(&g_done, 1);
        slastf = (d == B - 1);
    }
    __syncthreads();

    if (slastf) {                                  // very last: finalize
        __threadfence();
        float ns = 0.0f, npv = 0.0f;
        if (tid < B) {
            ns = *(volatile float*)&g_neg_sum[tid];
            npv = (float)*(volatile int*)&g_num_pos[tid];
        }
#pragma unroll
        for (int off = 16; off; off >>= 1) {
            ns += __shfl_xor_sync(0xFFFFFFFFu, ns, off);
            npv += __shfl_xor_sync(0xFFFFFFFFu, npv, off);
        }
        __shared__ float a2[2], c2[2];
        if (tid < B && (tid & 31) == 0) { a2[tid >> 5] = ns; c2[tid >> 5] = npv; }
        __syncthreads();
        if (tid == 0) {
            float totns = a2[0] + a2[1];
            float n = c2[0] + c2[1];
            out[0] = (*(volatile float*)&g_pos_ce + totns) / n;
            out[1] = (*(volatile float*)&g_sl1) / n;
        }
    }
}

// ---------------- launch ------------------------------------------------------
extern "C" void kernel_launch(void* const* d_in, const int* in_sizes, int n_in,
                              void* d_out, int out_size) {
    const float* locs   = (const float*)d_in[0];   // [B,P,4]
    const float* scores = (const float*)d_in[1];   // [B,P,C]
    const float* boxes  = (const float*)d_in[2];   // [B,O,4] xy
    const int*   labels = (const int*)  d_in[3];   // [B,O]
    const float* priors = (const float*)d_in[4];   // [P,4] cxcywh
    float* out = (float*)d_out;

    fused_kernel<<<GRID_TOTAL, 512>>>(scores, boxes, labels, priors);
    tail_kernel<<<dim3(TSLICE, B), 512>>>(locs, scores, boxes, labels, priors, out);
}

// round 16
// speedup vs baseline: 1.2831x; 1.2831x over previous
#include <cuda_runtime.h>
#include <cuda_pipeline.h>
#include <cstdint>

#define B 64
#define P 8732
#define C 81
#define O 32
#define RPB 128            // rows per lse block (B*P = 558848 = 128*4366)
#define NSLICE 16          // match blocks per batch item
#define BATCH_STRIDE (NSLICE * 16 * 32)   // 8192 priors per warp-sweep
#define NMATCH (NSLICE * B)               // 1024 match blocks
#define NLSE (B * P / RPB)                // 4366 lse blocks
#define GRID_TOTAL (NMATCH + NLSE)        // 5390
#define TSLICE 8                          // sweep blocks per batch
#define TCHUNK 1092                       // ceil(P/TSLICE)

#define NEG_INF (__int_as_float(0xff800000))

// ---------------- scratch (device globals; no allocation anywhere) ----------
__device__ unsigned long long g_obj_slice[B * NSLICE * O]; // (ov_bits<<32)|~p
__device__ int   g_match[B * P];                 // packed (obj<<8)|tc per prior
__device__ float g_lse[B * P];
__device__ float g_bg[B * P];                    // lse - s0
__device__ float g_mined[B * P];
__device__ int   g_num_pos[B];
__device__ float g_neg_sum[B];
__device__ float g_pos_ce;
__device__ float g_sl1;
__device__ int   g_done;

// ---------------- helpers ----------------------------------------------------
__device__ __forceinline__ unsigned okey(float f) {
    unsigned u = __float_as_uint(f);
    return (u & 0x80000000u) ? ~u : (u | 0x80000000u);
}
__device__ __forceinline__ float fromkey(unsigned k) {
    unsigned u = (k & 0x80000000u) ? (k & 0x7FFFFFFFu) : ~k;
    return __uint_as_float(u);
}
__device__ __forceinline__ float smoothl1(float d) {
    float a = fabsf(d);
    return (a < 1.0f) ? 0.5f * a * a : a - 0.5f;
}

// ---------------- K1: role-partitioned fused kernel (R13-proven) -------------
__global__ void __launch_bounds__(512, 2) fused_kernel(
        const float* __restrict__ scores,
        const float* __restrict__ boxes,
        const int*   __restrict__ labels,
        const float* __restrict__ priors) {
    int bid = blockIdx.x;
    int tid = threadIdx.x;
    bool is_match = (bid % 5 == 0) && (bid < 5 * NMATCH);

    if (is_match) {
        int mid = bid / 5;               // 0..1023
        int b = mid >> 4;                // batch
        int blk = mid & 15;              // slice
        int wid = tid >> 5;
        int lane = tid & 31;
        __shared__ float4 sbox[O];
        __shared__ float  sarea[O];
        __shared__ int    slab[O];
        __shared__ unsigned swkey[16][O];
        if (tid < O) {
            float4 bx = ((const float4*)boxes)[b * O + tid];
            sbox[tid] = bx;
            sarea[tid] = (bx.z - bx.x) * (bx.w - bx.y);
            slab[tid] = labels[b * O + tid];
        }
        if (mid == 0) {                  // init accumulators consumed downstream
            if (tid < B) { g_num_pos[tid] = 0; g_neg_sum[tid] = 0.0f; }
            if (tid == 0) { g_pos_ce = 0.0f; g_sl1 = 0.0f; g_done = 0; }
        }
        __syncthreads();

        int gwarp = blk * 16 + wid;
        unsigned runB = 0u;

        for (int batch = 0; batch < 2; batch++) {
            int pbase = batch * BATCH_STRIDE + gwarp * 32;
            if (pbase >= P) break;
            int p = pbase + lane;
            bool valid = (p < P);
            int pc = valid ? p : (P - 1);

            float4 pr = ((const float4*)priors)[pc];
            float px0 = pr.x - 0.5f * pr.z, py0 = pr.y - 0.5f * pr.w;
            float px1 = pr.x + 0.5f * pr.z, py1 = pr.y + 0.5f * pr.w;
            float parea = pr.z * pr.w;

            unsigned bestA = 0u;
#pragma unroll
            for (int o = 0; o < O; o++) {
                float4 bx = sbox[o];
                float lx = fmaxf(bx.x, px0), ly = fmaxf(bx.y, py0);
                float hx = fminf(bx.z, px1), hy = fminf(bx.w, py1);
                float w = fmaxf(hx - lx, 0.0f), h = fmaxf(hy - ly, 0.0f);
                float inter = w * h;
                float ov = __fdividef(inter, sarea[o] + parea - inter);
                unsigned ob = __float_as_uint(ov);
                bestA = max(bestA, (ob & 0xFFFFFFE0u) | (unsigned)(31 - o));
                unsigned keyB = valid
                    ? ((ob & 0xFFFFFF80u) | (unsigned)((3 - batch) << 5) | (unsigned)(31 - lane))
                    : 0u;
                unsigned m = __reduce_max_sync(0xFFFFFFFFu, keyB);
                if (lane == o) runB = max(runB, m);
            }
            if (valid) {
                int bo = 31 - (int)(bestA & 31u);
                float bov = __uint_as_float(bestA & 0xFFFFFFE0u);
                int tc = (bov < 0.5f) ? 0 : slab[bo];
                g_match[b * P + p] = (bo << 8) | tc;
            }
        }

        swkey[wid][lane] = runB;
        __syncthreads();

        if (tid < O) {
            int o = tid;
            unsigned long long best = 0ULL;
#pragma unroll
            for (int w = 0; w < 16; w++) {
                unsigned k = swkey[w][o];
                int batch = 3 - (int)((k >> 5) & 3u);
                int ln = 31 - (int)(k & 31u);
                unsigned p = (unsigned)(batch * BATCH_STRIDE + (blk * 16 + w) * 32 + ln);
                unsigned long long cand =
                    ((unsigned long long)(k & 0xFFFFFF80u) << 32) | (0xFFFFFFFFu - p);
                if (cand > best) best = cand;
            }
            g_obj_slice[(b * NSLICE + blk) * O + o] = best;
        }
    } else {
        // LSE role: pure streaming
        int lse_id = bid - min((bid + 4) / 5, NMATCH);   // 0..4365
        __shared__ __align__(16) float sm[RPB * C];      // 41472 bytes
        int wid = tid >> 5;
        int lane = tid & 31;
        size_t row0 = (size_t)lse_id * RPB;

        {
            const char* gsrc = (const char*)(scores + (row0 + wid * 8) * C);
            char* sdst = (char*)(sm + wid * 8 * C);
#pragma unroll
            for (int i = lane; i < 162; i += 32)
                __pipeline_memcpy_async(sdst + i * 16, gsrc + i * 16, 16);
            __pipeline_commit();
            __pipeline_wait_prior(0);
            __syncwarp();
        }

        int k = tid >> 2;
        int q = tid & 3;
        const float* my = sm + k * C;

        float sa[4] = {0.f, 0.f, 0.f, 0.f};
#pragma unroll
        for (int it = 0; it < 24; it++) {
            int g = it >> 3, e = it & 7;
            int j = g * 32 + (q << 3) + e;
            if (j < C) sa[it & 3] += __expf(my[j]);
        }
        float sum = (sa[0] + sa[1]) + (sa[2] + sa[3]);
        sum += __shfl_xor_sync(0xFFFFFFFFu, sum, 1);
        sum += __shfl_xor_sync(0xFFFFFFFFu, sum, 2);
        float lse = __logf(sum);

        if (q == 0) {
            int r = (int)row0 + k;
            g_lse[r] = lse;
            g_bg[r] = lse - my[0];
        }
    }
}

// ---------------- K2: lean sweep — fold + losses + mined ---------------------
__global__ void __launch_bounds__(256) sweep_kernel(
        const float* __restrict__ locs,
        const float* __restrict__ scores,
        const float* __restrict__ boxes,
        const int*   __restrict__ labels,
        const float* __restrict__ priors) {
    int s = blockIdx.x;                            // slice 0..7
    int b = blockIdx.y;                            // batch
    int tid = threadIdx.x;

    __shared__ unsigned spF[O];
    __shared__ int slabF[O];
    __shared__ int s_np;
    __shared__ float s_ce, s_sl1;

    if (tid < O) {
        unsigned long long m = 0ULL;
#pragma unroll
        for (int sl = 0; sl < NSLICE; sl++)
            m = max(m, g_obj_slice[(b * NSLICE + sl) * O + tid]);
        spF[tid] = 0xFFFFFFFFu - (unsigned)(m & 0xFFFFFFFFu);
        slabF[tid] = labels[b * O + tid];
    }
    if (tid == 0) { s_np = 0; s_ce = 0.0f; s_sl1 = 0.0f; }
    __syncthreads();

    int pstart = s * TCHUNK;
    int pend = min(P, pstart + TCHUNK);

    for (int p = pstart + tid; p < pend; p += 256) {
        int r = b * P + p;
        int mm = g_match[r];
        int tc = mm & 0xFF;
        int obj = mm >> 8;
#pragma unroll
        for (int o = 0; o < O; o++) {              // ascending: last (highest o) wins
            if (spF[o] == (unsigned)p) { tc = slabF[o]; obj = o; }
        }
        float mined;
        if (tc > 0) {
            float lse = g_lse[r];
            float stc = scores[(size_t)r * C + tc];
            atomicAdd(&s_ce, lse - stc);
            atomicAdd(&s_np, 1);
            float4 bx = ((const float4*)boxes)[b * O + obj];
            float4 pr = ((const float4*)priors)[p];
            float cx = 0.5f * (bx.x + bx.z), cy = 0.5f * (bx.y + bx.w);
            float w = bx.z - bx.x, h = bx.w - bx.y;
            float t0 = (cx - pr.x) * 10.0f / pr.z;
            float t1 = (cy - pr.y) * 10.0f / pr.w;
            float t2 = __logf(w / pr.z) * 5.0f;
            float t3 = __logf(h / pr.w) * 5.0f;
            float4 pl = ((const float4*)locs)[r];
            float sl = smoothl1(pl.x - t0) + smoothl1(pl.y - t1) +
                       smoothl1(pl.z - t2) + smoothl1(pl.w - t3);
            atomicAdd(&s_sl1, sl);
            mined = NEG_INF;
        } else {
            mined = g_bg[r];
        }
        g_mined[r] = mined;
    }
    __syncthreads();

    if (tid == 0) {
        if (s_np) atomicAdd(&g_num_pos[b], s_np);
        atomicAdd(&g_pos_ce, s_ce);
        atomicAdd(&g_sl1, s_sl1);
    }
}

// ---------------- K3: per-batch smem radix-select + finalize -----------------
__global__ void __launch_bounds__(512) select_kernel(float* __restrict__ out) {
    int b = blockIdx.x;
    int tid = threadIdx.x;

    __shared__ float sm_mined[P];                  // 34928 B
    __shared__ int hist[256];
    __shared__ int ssum[256];
    __shared__ int wtot[8];
    __shared__ unsigned sprefix;
    __shared__ int sK;
    __shared__ float swsum[16];
    __shared__ int slastf;

    for (int p = tid; p < P; p += 512)
        sm_mined[p] = g_mined[b * P + p];
    int np = g_num_pos[b];
    int K = min(3 * np, P - np);
    float result = 0.0f;
    __syncthreads();

    if (K > 0) {
        if (tid == 0) { sprefix = 0u; sK = K; }
        __syncthreads();
        for (int shift = 24; shift >= 0; shift -= 8) {
            if (tid < 256) hist[tid] = 0;
            __syncthreads();
            unsigned prefix = sprefix;
            int Kr = sK;
            for (int p = tid; p < P; p += 512) {
                unsigned k = okey(sm_mined[p]);
                if (shift == 24 || (k >> (shift + 8)) == prefix)
                    atomicAdd(&hist[(k >> shift) & 255u], 1);
            }
            __syncthreads();
            int v = 0;
            int w = tid >> 5, l = tid & 31;
            if (tid < 256) {                       // warp-level suffix scan
                v = hist[tid];
#pragma unroll
                for (int off = 1; off < 32; off <<= 1) {
                    int u = __shfl_down_sync(0xFFFFFFFFu, v, off);
                    if (l + off < 32) v += u;
                }
                if (l == 0) wtot[w] = v;
            }
            __syncthreads();
            if (tid < 256) {
                int add = 0;
#pragma unroll
                for (int g = 1; g < 8; g++) if (w + g < 8) add += wtot[w + g];
                ssum[tid] = v + add;
            }
            __syncthreads();
            if (tid < 256) {
                int mine = ssum[tid];
                int nxt = (tid < 255) ? ssum[tid + 1] : 0;
                if (mine >= Kr && nxt < Kr) {
                    sprefix = (prefix << 8) | (unsigned)tid;
                    sK = Kr - nxt;
                }
            }
            __syncthreads();
        }
        unsigned T = sprefix;
        int rr = sK;
        float Tval = fromkey(T);

        float sum = 0.0f;
        for (int p = tid; p < P; p += 512) {
            float v2 = sm_mined[p];
            if (okey(v2) > T) sum += v2;
        }
#pragma unroll
        for (int off = 16; off; off >>= 1) sum += __shfl_xor_sync(0xFFFFFFFFu, sum, off);
        if ((tid & 31) == 0) swsum[tid >> 5] = sum;
        __syncthreads();
        if (tid == 0) {
            float tot = 0.0f;
#pragma unroll
            for (int i = 0; i < 16; i++) tot += swsum[i];
            result = tot + (float)rr * Tval;
        }
    }

    if (tid == 0) {
        g_neg_sum[b] = result;
        __threadfence();
        int d = atomicAdd(&g_done, 1);
        slastf = (d == B - 1);
    }
    __syncthreads();

    if (slastf) {                                  // very last: finalize
        __threadfence();
        float ns = 0.0f, npv = 0.0f;
        if (tid < B) {
            ns = *(volatile float*)&g_neg_sum[tid];
            npv = (float)*(volatile int*)&g_num_pos[tid];
        }
#pragma unroll
        for (int off = 16; off; off >>= 1) {
            ns += __shfl_xor_sync(0xFFFFFFFFu, ns, off);
            npv += __shfl_xor_sync(0xFFFFFFFFu, npv, off);
        }
        __shared__ float a2[2], c2[2];
        if (tid < B && (tid & 31) == 0) { a2[tid >> 5] = ns; c2[tid >> 5] = npv; }
        __syncthreads();
        if (tid == 0) {
            float totns = a2[0] + a2[1];
            float n = c2[0] + c2[1];
            out[0] = (*(volatile float*)&g_pos_ce + totns) / n;
            out[1] = (*(volatile float*)&g_sl1) / n;
        }
    }
}

// ---------------- launch ------------------------------------------------------
extern "C" void kernel_launch(void* const* d_in, const int* in_sizes, int n_in,
                              void* d_out, int out_size) {
    const float* locs   = (const float*)d_in[0];   // [B,P,4]
    const float* scores = (const float*)d_in[1];   // [B,P,C]
    const float* boxes  = (const float*)d_in[2];   // [B,O,4] xy
    const int*   labels = (const int*)  d_in[3];   // [B,O]
    const float* priors = (const float*)d_in[4];   // [P,4] cxcywh
    float* out = (float*)d_out;

    fused_kernel<<<GRID_TOTAL, 512>>>(scores, boxes, labels, priors);
    sweep_kernel<<<dim3(TSLICE, B), 256>>>(locs, scores, boxes, labels, priors);
    select_kernel<<<B, 512>>>(out);
}